// round 6
// baseline (speedup 1.0000x reference)
#include <cuda_runtime.h>
#include <cstdint>

#define NN 100000
#define F1 128
#define FH 64
#define FO 32
#define EMAX 1600000
#define NSCAN_BLK 196            // ceil(100000/512)

// Scratch (no allocations allowed).
__device__ int   g_deg[NN];
__device__ int   g_cur[NN];
__device__ int   g_off[NN];
__device__ int   g_scan[NN];
__device__ int   g_bsum[NSCAN_BLK];
__device__ int   g_bsumx[NSCAN_BLK];
__device__ float g_dinv[NN];
__device__ int2  g_edge[EMAX];            // (src, norm) grouped by dst
__device__ float g_h1[(size_t)NN * FH];   // x @ W1
__device__ float g_a1[(size_t)NN * FH];   // layer-1 activations (post ReLU)
__device__ float g_h3[(size_t)NN * FO];   // a1 @ W2

// ---------------------------------------------------------------------------
__global__ void k_init() {
    int i = blockIdx.x * blockDim.x + threadIdx.x;
    if (i < NN) g_deg[i] = 0;
}

__global__ void k_deg(const int* __restrict__ ei, int E) {
    int i = blockIdx.x * blockDim.x + threadIdx.x;
    if (i < E) atomicAdd(&g_deg[ei[E + i]], 1);
}

__global__ void k_dinv() {
    int i = blockIdx.x * blockDim.x + threadIdx.x;
    if (i < NN) g_dinv[i] = rsqrtf((float)g_deg[i] + 1.0f);  // +1 self-loop
}

// ---- exclusive prefix sum of g_deg -> g_off --------------------------------
__global__ __launch_bounds__(512) void k_scan1() {
    __shared__ int sh[512];
    int t = threadIdx.x;
    int i = blockIdx.x * 512 + t;
    int v = (i < NN) ? g_deg[i] : 0;
    sh[t] = v;
    for (int d = 1; d < 512; d <<= 1) {
        __syncthreads();
        int u = (t >= d) ? sh[t - d] : 0;
        __syncthreads();
        sh[t] += u;
    }
    __syncthreads();
    if (i < NN) g_scan[i] = sh[t];
    if (t == 511) g_bsum[blockIdx.x] = sh[511];
}

__global__ __launch_bounds__(256) void k_scan2() {
    __shared__ int sh[256];
    int t = threadIdx.x;
    int v = (t < NSCAN_BLK) ? g_bsum[t] : 0;
    sh[t] = v;
    for (int d = 1; d < 256; d <<= 1) {
        __syncthreads();
        int u = (t >= d) ? sh[t - d] : 0;
        __syncthreads();
        sh[t] += u;
    }
    __syncthreads();
    if (t < NSCAN_BLK) g_bsumx[t] = sh[t] - v;   // exclusive
}

__global__ void k_scan3() {
    int i = blockIdx.x * blockDim.x + threadIdx.x;
    if (i >= NN) return;
    g_off[i] = g_scan[i] - g_deg[i] + g_bsumx[i >> 9];  // exclusive offset
    g_cur[i] = 0;
}

// Scatter edges into destination-grouped order, packing (src, norm).
__global__ void k_scatter(const int* __restrict__ ei, int E) {
    int e = blockIdx.x * blockDim.x + threadIdx.x;
    if (e >= E) return;
    int s = ei[e];
    int d = ei[E + e];
    float norm = g_dinv[s] * g_dinv[d];
    int pos = g_off[d] + atomicAdd(&g_cur[d], 1);
    g_edge[pos] = make_int2(s, __float_as_int(norm));
}

// ---------------------------------------------------------------------------
// GEMM1: h1[NN,64] = x[NN,128] @ W1[128,64]. 128 rows/block, 4x8 reg tile.
__global__ __launch_bounds__(256) void k_gemm1(const float* __restrict__ x,
                                               const float* __restrict__ W) {
    extern __shared__ float dyn[];
    float* Ws = dyn;                 // [128][64]  32 KB
    float* xs = dyn + F1 * FH;       // [128][128] 64 KB
    int tid = threadIdx.x;
    float4* Ws4 = (float4*)Ws;
    const float4* W4 = (const float4*)W;
    for (int i = tid; i < F1 * FH / 4; i += 256) Ws4[i] = W4[i];
    int row0 = blockIdx.x * 128;
    float4* xs4 = (float4*)xs;
    const float4* x4 = (const float4*)x;
    for (int i = tid; i < 128 * F1 / 4; i += 256) {
        int row = row0 + (i >> 5);                 // 32 float4 per row
        xs4[i] = (row < NN) ? x4[(size_t)row * 32 + (i & 31)]
                            : make_float4(0.f, 0.f, 0.f, 0.f);
    }
    __syncthreads();

    int tx = tid & 7;               // cols 8tx..8tx+7 (two float4)
    int ty = tid >> 3;              // rows 4ty..4ty+3
    const float* xr = xs + 4 * ty * F1;
    float4 acc[4][2] = {};
    #pragma unroll 4
    for (int k = 0; k < F1; k++) {
        float4 w0 = Ws4[k * 16 + 2 * tx];
        float4 w1 = Ws4[k * 16 + 2 * tx + 1];
        #pragma unroll
        for (int j = 0; j < 4; j++) {
            float a = xr[j * F1 + k];
            acc[j][0].x = fmaf(a, w0.x, acc[j][0].x);
            acc[j][0].y = fmaf(a, w0.y, acc[j][0].y);
            acc[j][0].z = fmaf(a, w0.z, acc[j][0].z);
            acc[j][0].w = fmaf(a, w0.w, acc[j][0].w);
            acc[j][1].x = fmaf(a, w1.x, acc[j][1].x);
            acc[j][1].y = fmaf(a, w1.y, acc[j][1].y);
            acc[j][1].z = fmaf(a, w1.z, acc[j][1].z);
            acc[j][1].w = fmaf(a, w1.w, acc[j][1].w);
        }
    }
    float4* h1v = (float4*)g_h1;
    #pragma unroll
    for (int j = 0; j < 4; j++) {
        int row = row0 + 4 * ty + j;
        if (row < NN) {
            h1v[(size_t)row * 16 + 2 * tx]     = acc[j][0];
            h1v[(size_t)row * 16 + 2 * tx + 1] = acc[j][1];
        }
    }
}

// Aggregation layer 1 (+ self-loop + bias + ReLU): one warp per dst node.
__global__ __launch_bounds__(256) void k_agg1(const float* __restrict__ b1) {
    int node = (blockIdx.x * 256 + threadIdx.x) >> 5;
    int lane = threadIdx.x & 31;
    if (node >= NN) return;
    int off = g_off[node];
    int n   = g_deg[node];
    const float2* h1v = (const float2*)g_h1;
    float2 acc = make_float2(0.f, 0.f);
    int i = 0;
    for (; i + 4 <= n; i += 4) {
        int2 e0 = g_edge[off + i];
        int2 e1 = g_edge[off + i + 1];
        int2 e2 = g_edge[off + i + 2];
        int2 e3 = g_edge[off + i + 3];
        float2 p0 = h1v[(size_t)e0.x * 32 + lane];
        float2 p1 = h1v[(size_t)e1.x * 32 + lane];
        float2 p2 = h1v[(size_t)e2.x * 32 + lane];
        float2 p3 = h1v[(size_t)e3.x * 32 + lane];
        float n0 = __int_as_float(e0.y), n1 = __int_as_float(e1.y);
        float n2 = __int_as_float(e2.y), n3 = __int_as_float(e3.y);
        acc.x = fmaf(p0.x, n0, acc.x); acc.y = fmaf(p0.y, n0, acc.y);
        acc.x = fmaf(p1.x, n1, acc.x); acc.y = fmaf(p1.y, n1, acc.y);
        acc.x = fmaf(p2.x, n2, acc.x); acc.y = fmaf(p2.y, n2, acc.y);
        acc.x = fmaf(p3.x, n3, acc.x); acc.y = fmaf(p3.y, n3, acc.y);
    }
    for (; i < n; i++) {
        int2 e0 = g_edge[off + i];
        float2 p = h1v[(size_t)e0.x * 32 + lane];
        float n0 = __int_as_float(e0.y);
        acc.x = fmaf(p.x, n0, acc.x); acc.y = fmaf(p.y, n0, acc.y);
    }
    float di = g_dinv[node], w = di * di;
    float2 hs = h1v[(size_t)node * 32 + lane];
    float2 bb = ((const float2*)b1)[lane];
    acc.x = fmaxf(fmaf(hs.x, w, acc.x) + bb.x, 0.f);
    acc.y = fmaxf(fmaf(hs.y, w, acc.y) + bb.y, 0.f);
    ((float2*)g_a1)[(size_t)node * 32 + lane] = acc;
}

// ---------------------------------------------------------------------------
// GEMM2: h3[NN,32] = a1[NN,64] @ W2[64,32]. 256 rows/block, 4x8 reg tile.
__global__ __launch_bounds__(256) void k_gemm2(const float* __restrict__ W) {
    extern __shared__ float dyn[];
    float* Ws = dyn;                 // [64][32]   8 KB
    float* xs = dyn + FH * FO;       // [256][64] 64 KB
    int tid = threadIdx.x;
    float4* Ws4 = (float4*)Ws;
    const float4* W4 = (const float4*)W;
    for (int i = tid; i < FH * FO / 4; i += 256) Ws4[i] = W4[i];
    int row0 = blockIdx.x * 256;
    float4* xs4 = (float4*)xs;
    const float4* x4 = (const float4*)g_a1;
    for (int i = tid; i < 256 * FH / 4; i += 256) {
        int row = row0 + (i >> 4);                 // 16 float4 per row
        xs4[i] = (row < NN) ? x4[(size_t)row * 16 + (i & 15)]
                            : make_float4(0.f, 0.f, 0.f, 0.f);
    }
    __syncthreads();

    int tx = tid & 3;               // cols 8tx..8tx+7
    int ty = tid >> 2;              // rows 4ty..4ty+3
    const float* xr = xs + 4 * ty * FH;
    float4 acc[4][2] = {};
    #pragma unroll 4
    for (int k = 0; k < FH; k++) {
        float4 w0 = Ws4[k * 8 + 2 * tx];
        float4 w1 = Ws4[k * 8 + 2 * tx + 1];
        #pragma unroll
        for (int j = 0; j < 4; j++) {
            float a = xr[j * FH + k];
            acc[j][0].x = fmaf(a, w0.x, acc[j][0].x);
            acc[j][0].y = fmaf(a, w0.y, acc[j][0].y);
            acc[j][0].z = fmaf(a, w0.z, acc[j][0].z);
            acc[j][0].w = fmaf(a, w0.w, acc[j][0].w);
            acc[j][1].x = fmaf(a, w1.x, acc[j][1].x);
            acc[j][1].y = fmaf(a, w1.y, acc[j][1].y);
            acc[j][1].z = fmaf(a, w1.z, acc[j][1].z);
            acc[j][1].w = fmaf(a, w1.w, acc[j][1].w);
        }
    }
    float4* h3v = (float4*)g_h3;
    #pragma unroll
    for (int j = 0; j < 4; j++) {
        int row = row0 + 4 * ty + j;
        if (row < NN) {
            h3v[(size_t)row * 8 + 2 * tx]     = acc[j][0];
            h3v[(size_t)row * 8 + 2 * tx + 1] = acc[j][1];
        }
    }
}

// Aggregation layer 2 (+ self-loop + bias): one warp per dst node, writes d_out.
__global__ __launch_bounds__(256) void k_agg2(float* __restrict__ out,
                                              const float* __restrict__ b2) {
    int node = (blockIdx.x * 256 + threadIdx.x) >> 5;
    int lane = threadIdx.x & 31;
    if (node >= NN) return;
    int off = g_off[node];
    int n   = g_deg[node];
    float acc = 0.f;
    int i = 0;
    for (; i + 4 <= n; i += 4) {
        int2 e0 = g_edge[off + i];
        int2 e1 = g_edge[off + i + 1];
        int2 e2 = g_edge[off + i + 2];
        int2 e3 = g_edge[off + i + 3];
        float p0 = g_h3[(size_t)e0.x * 32 + lane];
        float p1 = g_h3[(size_t)e1.x * 32 + lane];
        float p2 = g_h3[(size_t)e2.x * 32 + lane];
        float p3 = g_h3[(size_t)e3.x * 32 + lane];
        acc = fmaf(p0, __int_as_float(e0.y), acc);
        acc = fmaf(p1, __int_as_float(e1.y), acc);
        acc = fmaf(p2, __int_as_float(e2.y), acc);
        acc = fmaf(p3, __int_as_float(e3.y), acc);
    }
    for (; i < n; i++) {
        int2 e0 = g_edge[off + i];
        acc = fmaf(g_h3[(size_t)e0.x * 32 + lane], __int_as_float(e0.y), acc);
    }
    float di = g_dinv[node], w = di * di;
    out[(size_t)node * 32 + lane] =
        fmaf(g_h3[(size_t)node * 32 + lane], w, acc) + b2[lane];
}

// ---------------------------------------------------------------------------
namespace {
struct Ctx {
    cudaStream_t s2;
    cudaEvent_t e_fork, e_join;
    Ctx() {
        cudaStreamCreateWithFlags(&s2, cudaStreamNonBlocking);
        cudaEventCreateWithFlags(&e_fork, cudaEventDisableTiming);
        cudaEventCreateWithFlags(&e_join, cudaEventDisableTiming);
        cudaFuncSetAttribute(k_gemm1, cudaFuncAttributeMaxDynamicSharedMemorySize,
                             (F1 * FH + 128 * F1) * 4);
        cudaFuncSetAttribute(k_gemm2, cudaFuncAttributeMaxDynamicSharedMemorySize,
                             (FH * FO + 256 * FH) * 4);
    }
};
}

extern "C" void kernel_launch(void* const* d_in, const int* in_sizes, int n_in,
                              void* d_out, int out_size) {
    static Ctx ctx;   // created on first (uncaptured) correctness call

    const float* x  = (const float*)d_in[0];
    const int*   ei = (const int*)d_in[1];     // int32 (JAX x64 disabled)
    const float* W1 = (const float*)d_in[2];
    const float* b1 = (const float*)d_in[3];
    const float* W2 = (const float*)d_in[4];
    const float* b2 = (const float*)d_in[5];
    float* out = (float*)d_out;

    const int E = in_sizes[1] / 2;

    // Fork: preprocessing chain on ctx.s2, GEMM1 on the main stream.
    cudaEventRecord(ctx.e_fork, 0);
    cudaStreamWaitEvent(ctx.s2, ctx.e_fork, 0);

    k_init<<<(NN + 255) / 256, 256, 0, ctx.s2>>>();
    k_deg<<<(E + 255) / 256, 256, 0, ctx.s2>>>(ei, E);
    k_dinv<<<(NN + 255) / 256, 256, 0, ctx.s2>>>();
    k_scan1<<<NSCAN_BLK, 512, 0, ctx.s2>>>();
    k_scan2<<<1, 256, 0, ctx.s2>>>();
    k_scan3<<<(NN + 255) / 256, 256, 0, ctx.s2>>>();
    k_scatter<<<(E + 255) / 256, 256, 0, ctx.s2>>>(ei, E);
    cudaEventRecord(ctx.e_join, ctx.s2);

    k_gemm1<<<(NN + 127) / 128, 256, (F1 * FH + 128 * F1) * 4>>>(x, W1);

    // Join: aggregation needs both h1 and the sorted edge list.
    cudaStreamWaitEvent(0, ctx.e_join, 0);

    k_agg1<<<(NN * 32 + 255) / 256, 256>>>(b1);
    k_gemm2<<<(NN + 255) / 256, 256, (FH * FO + 256 * FH) * 4>>>(W2);
    k_agg2<<<(NN * 32 + 255) / 256, 256>>>(out, b2);
}